// round 16
// baseline (speedup 1.0000x reference)
#include <cuda_runtime.h>
#include <cuda_fp16.h>

#define NN 100000
#define EE 1600000
#define C  64

#define SCAN_B 512
#define SCAN_NB ((NN + SCAN_B - 1) / SCAN_B)   // 196

// padded CSR (src-only): every node segment rounded up to multiple of 8
#define ECAP_E (EE + 8 * NN)                   // 2.4M ints
#define ZR (NN * 32)                           // zero feature row base word

#define RPW 4
#define GEMM_BLKS ((NN / RPW) * 32 / 256)      // 3125
#define HIST_BLKS 2048
#define CLR_BLKS  512
#define FILL_BLKS 1536
#define SCALE_BLKS 512

// ---- scratch (device globals) ----
__device__ int       g_deg[NN];
__device__ int       g_off[NN];
__device__ int       g_cur[NN];
__device__ float     g_dis[NN];
__device__ int       g_bsum[SCAN_NB];
__device__ __align__(16) int g_srci[ECAP_E];        // src*32 per edge slot (pad -> ZR)
__device__ unsigned  g_xwh[(size_t)NN * 32 + 32];   // features half2-packed + zero row
__device__ float     g_x [(size_t)NN * C];          // activations (fp32)
__device__ double    g_stats[2];

// ---------------- init: deg=0, stats=0, zero feature row ----------------
__global__ void k_init0() {
    int i = blockIdx.x * blockDim.x + threadIdx.x;
    if (i < NN) g_deg[i] = 0;
    if (i < 2)  g_stats[i] = 0.0;
    if (i < 32) g_xwh[ZR + i] = 0u;
}

// ---------------- gemm device body (verified form) ----------------
__device__ __forceinline__ void gemm_body(const float* __restrict__ Xin,
                                          const float* __restrict__ W,
                                          int gblk, int scale_by_dis) {
    __shared__ float2 Wp[C][32];    // (W[k][2l], W[k][2l+1])
    __shared__ float4 Xs[8][C];     // Xs[warp][k] = 4 rows' col k
    for (int i = threadIdx.x; i < C * 32; i += blockDim.x) {
        int k = i >> 5, l = i & 31;
        Wp[k][l] = make_float2(W[k * C + 2 * l], W[k * C + 2 * l + 1]);
    }

    int warp = (gblk * 256 + threadIdx.x) >> 5;
    int w    = threadIdx.x >> 5;
    int lane = threadIdx.x & 31;
    int r0 = warp * RPW;

    {
        float2 xv[RPW];
#pragma unroll
        for (int i = 0; i < RPW; i++)
            xv[i] = *(const float2*)(Xin + (size_t)(r0 + i) * C + 2 * lane);
        Xs[w][2 * lane]     = make_float4(xv[0].x, xv[1].x, xv[2].x, xv[3].x);
        Xs[w][2 * lane + 1] = make_float4(xv[0].y, xv[1].y, xv[2].y, xv[3].y);
    }
    __syncthreads();

    float a0[RPW] = {0.f, 0.f, 0.f, 0.f};
    float a1[RPW] = {0.f, 0.f, 0.f, 0.f};
#pragma unroll
    for (int k = 0; k < C; k++) {
        float4 xk = Xs[w][k];          // LDS.128 broadcast
        float2 wv = Wp[k][lane];       // LDS.64 conflict-free
        a0[0] += xk.x * wv.x;  a1[0] += xk.x * wv.y;
        a0[1] += xk.y * wv.x;  a1[1] += xk.y * wv.y;
        a0[2] += xk.z * wv.x;  a1[2] += xk.z * wv.y;
        a0[3] += xk.w * wv.x;  a1[3] += xk.w * wv.y;
    }
#pragma unroll
    for (int i = 0; i < RPW; i++) {
        float d = scale_by_dis ? g_dis[r0 + i] : 1.0f;
        __half2 h = __float22half2_rn(make_float2(a0[i] * d, a1[i] * d));
        g_xwh[(size_t)(r0 + i) * 32 + lane] = *(unsigned*)&h;
    }
}

// ---------------- merged: gemm layer-1 + dst histogram + edge-array preset ----------------
__global__ void k_gemm_hist_clr(const float* __restrict__ X,
                                const float* __restrict__ W1,
                                const int* __restrict__ dst) {
    if (blockIdx.x < GEMM_BLKS) {
        gemm_body(X, W1, blockIdx.x, 0);
    } else if (blockIdx.x < GEMM_BLKS + HIST_BLKS) {
        int tid = (blockIdx.x - GEMM_BLKS) * blockDim.x + threadIdx.x;
        int stride = HIST_BLKS * blockDim.x;
        for (int e = tid; e < EE; e += stride)
            atomicAdd(&g_deg[dst[e]], 1);
    } else {
        int tid = (blockIdx.x - GEMM_BLKS - HIST_BLKS) * blockDim.x + threadIdx.x;
        int stride = CLR_BLKS * blockDim.x;
        int4 z = make_int4(ZR, ZR, ZR, ZR);
        int4* p = (int4*)g_srci;
        for (int i = tid; i < ECAP_E / 4; i += stride) p[i] = z;
    }
}

// ---------------- scan A: block-local exclusive scan of pad8(deg+1) ----------------
__global__ void k_scan_a() {
    __shared__ int sh[SCAN_B];
    int t = threadIdx.x;
    int i = blockIdx.x * SCAN_B + t;
    int v = (i < NN) ? ((g_deg[i] + 8) & ~7) : 0;
    sh[t] = v;
    __syncthreads();
    int acc = v;
#pragma unroll
    for (int d = 1; d < SCAN_B; d <<= 1) {
        int u = (t >= d) ? sh[t - d] : 0;
        __syncthreads();
        acc += u;
        sh[t] = acc;
        __syncthreads();
    }
    if (i < NN) g_off[i] = acc - v;
    if (t == SCAN_B - 1) g_bsum[blockIdx.x] = acc;
}

// ---------------- scan C (merged B): offsets, cur, dis; self-loop placed at slot off ----------------
__global__ void k_scan_c() {
    __shared__ int sh[256];
    int t = threadIdx.x;
    int v = (t < SCAN_NB) ? g_bsum[t] : 0;
    sh[t] = v;
    __syncthreads();
    int acc = v;
#pragma unroll
    for (int d = 1; d < 256; d <<= 1) {
        int u = (t >= d) ? sh[t - d] : 0;
        __syncthreads();
        acc += u;
        sh[t] = acc;
        __syncthreads();
    }
    sh[t] = acc - v;
    __syncthreads();

    int i = blockIdx.x * blockDim.x + t;
    if (i >= NN) return;
    int off = g_off[i] + sh[i / SCAN_B];
    g_off[i] = off;
    g_srci[off] = i * 32;            // self-loop in first slot (no atomic needed)
    g_cur[i] = off + 1;
    g_dis[i] = rsqrtf((float)(g_deg[i] + 1));
}

// ---------------- merged: CSR fill (vectorized, src only) + feature scale ----------------
__global__ void k_fill_scale(const int* __restrict__ src,
                             const int* __restrict__ dst) {
    if (blockIdx.x < FILL_BLKS) {
        int tid = blockIdx.x * blockDim.x + threadIdx.x;
        int stride = FILL_BLKS * blockDim.x;
        const int4* s4 = (const int4*)src;
        const int4* d4 = (const int4*)dst;
        for (int q = tid; q < EE / 4; q += stride) {    // EE divisible by 4
            int4 s = s4[q];
            int4 d = d4[q];
            g_srci[atomicAdd(&g_cur[d.x], 1)] = s.x * 32;
            g_srci[atomicAdd(&g_cur[d.y], 1)] = s.y * 32;
            g_srci[atomicAdd(&g_cur[d.z], 1)] = s.z * 32;
            g_srci[atomicAdd(&g_cur[d.w], 1)] = s.w * 32;
        }
    } else {
        // g_xwh[r] *= dis[r]
        int tid = (blockIdx.x - FILL_BLKS) * blockDim.x + threadIdx.x;
        int stride = SCALE_BLKS * blockDim.x;
        for (int i = tid; i < NN * 32; i += stride) {
            float d = g_dis[i >> 5];
            float2 v = __half22float2(*(__half2*)&g_xwh[i]);
            __half2 h = __float22half2_rn(make_float2(v.x * d, v.y * d));
            g_xwh[i] = *(unsigned*)&h;
        }
    }
}

// ---------------- gemm layer-2 (reads g_x, writes g_xwh pre-scaled by dis) ----------------
__global__ void k_gemm2(const float* __restrict__ W) {
    gemm_body(g_x, W, blockIdx.x, 1);
}

// ---------------- aggregate: warp/node, paired-row LDG.64 gathers ----------------
// lanes 0-15 gather even edges' rows, lanes 16-31 odd edges' rows; lane h=lane&15
// owns cols 4h..4h+3. shfl_xor(16) merges the two edge partitions.
__global__ void k_agg(const float* __restrict__ bias, int phase) {
    int node = (blockIdx.x * blockDim.x + threadIdx.x) >> 5;
    int lane = threadIdx.x & 31;
    int g    = lane >> 4;            // edge-parity group
    int h    = lane & 15;            // column quad

    int   off = g_off[node];         // multiple of 8
    int   nb  = (g_deg[node] + 8) >> 3;
    float di  = g_dis[node];

    float a0 = 0.f, a1 = 0.f, a2 = 0.f, a3 = 0.f;

    const int4* e4 = (const int4*)(g_srci + off);
    const unsigned* feat = g_xwh;

    for (int b = 0; b < nb; b++, e4 += 2) {
        int4 p0 = e4[0], p1 = e4[1];          // uniform LDG.128 x2 (8 edges)
        int r0 = g ? p0.y : p0.x;
        int r1 = g ? p0.w : p0.z;
        int r2 = g ? p1.y : p1.x;
        int r3 = g ? p1.w : p1.z;
        uint2 v0 = *(const uint2*)(feat + r0 + 2 * h);   // LDG.64: 2 rows/instr
        uint2 v1 = *(const uint2*)(feat + r1 + 2 * h);
        uint2 v2 = *(const uint2*)(feat + r2 + 2 * h);
        uint2 v3 = *(const uint2*)(feat + r3 + 2 * h);
#pragma unroll
        for (int q = 0; q < 4; q++) {
            uint2 v = (q == 0) ? v0 : (q == 1) ? v1 : (q == 2) ? v2 : v3;
            float2 f0 = __half22float2(*(__half2*)&v.x);
            float2 f1 = __half22float2(*(__half2*)&v.y);
            a0 += f0.x; a1 += f0.y;
            a2 += f1.x; a3 += f1.y;
        }
    }

    // merge even/odd edge partitions
    a0 += __shfl_xor_sync(0xffffffffu, a0, 16);
    a1 += __shfl_xor_sync(0xffffffffu, a1, 16);
    a2 += __shfl_xor_sync(0xffffffffu, a2, 16);
    a3 += __shfl_xor_sync(0xffffffffu, a3, 16);

    float4 bb = *(const float4*)(bias + 4 * h);
    float o0 = fmaxf(a0 * di + bb.x, 0.f);
    float o1 = fmaxf(a1 * di + bb.y, 0.f);
    float o2 = fmaxf(a2 * di + bb.z, 0.f);
    float o3 = fmaxf(a3 * di + bb.w, 0.f);

    if (g == 0)
        *(float4*)(g_x + (size_t)node * C + 4 * h) = make_float4(o0, o1, o2, o3);

    if (phase) {   // fused global sum/sumsq; group 0 lanes hold unique values
        float s = 0.f, s2 = 0.f;
        if (g == 0) {
            s  = o0 + o1 + o2 + o3;
            s2 = o0 * o0 + o1 * o1 + o2 * o2 + o3 * o3;
        }
#pragma unroll
        for (int o = 16; o; o >>= 1) {
            s  += __shfl_down_sync(0xffffffffu, s,  o);
            s2 += __shfl_down_sync(0xffffffffu, s2, o);
        }
        __shared__ float ss[8], ss2[8];
        int w = threadIdx.x >> 5;
        if (lane == 0) { ss[w] = s; ss2[w] = s2; }
        __syncthreads();
        if (w == 0 && lane < 8) {
            s  = ss[lane];
            s2 = ss2[lane];
#pragma unroll
            for (int o = 4; o; o >>= 1) {
                s  += __shfl_down_sync(0x000000ffu, s,  o);
                s2 += __shfl_down_sync(0x000000ffu, s2, o);
            }
            if (lane == 0) {
                atomicAdd(&g_stats[0], (double)s);
                atomicAdd(&g_stats[1], (double)s2);
            }
        }
    }
}

// ---------------- graph layernorm (float4) ----------------
__global__ void k_ln(const float* __restrict__ lnw,
                     const float* __restrict__ lnb,
                     float* __restrict__ out) {
    const int M4 = NN * C / 4;
    double mean = g_stats[0] / (double)(NN * C);
    double var  = g_stats[1] / (double)(NN * C) - mean * mean;
    float scale = (float)(1.0 / sqrt(var + 1e-5)) * lnw[0];
    float mu    = (float)mean;
    float shb   = lnb[0];
    const float4* xi = (const float4*)g_x;
    float4* xo = (float4*)out;
    int stride = gridDim.x * blockDim.x;
    for (int i = blockIdx.x * blockDim.x + threadIdx.x; i < M4; i += stride) {
        float4 v = xi[i];
        v.x = (v.x - mu) * scale + shb;
        v.y = (v.y - mu) * scale + shb;
        v.z = (v.z - mu) * scale + shb;
        v.w = (v.w - mu) * scale + shb;
        xo[i] = v;
    }
}

extern "C" void kernel_launch(void* const* d_in, const int* in_sizes, int n_in,
                              void* d_out, int out_size) {
    const float* X    = (const float*)d_in[0];
    const int*   edges= (const int*)d_in[1];   // int32 (JAX x64 disabled)
    const float* W1   = (const float*)d_in[2];
    const float* b1   = (const float*)d_in[3];
    const float* W2   = (const float*)d_in[4];
    const float* b2   = (const float*)d_in[5];
    const float* lnw  = (const float*)d_in[6];
    const float* lnb  = (const float*)d_in[7];
    float* out = (float*)d_out;

    const int* srcp = edges;        // edges[0]
    const int* dstp = edges + EE;   // edges[1]

    const int agg_grid = (NN * 32) / 256;      // exactly 12500

    k_init0<<<(NN + 255) / 256, 256>>>();
    k_gemm_hist_clr<<<GEMM_BLKS + HIST_BLKS + CLR_BLKS, 256>>>(X, W1, dstp);
    k_scan_a<<<SCAN_NB, SCAN_B>>>();
    k_scan_c<<<(NN + 255) / 256, 256>>>();
    k_fill_scale<<<FILL_BLKS + SCALE_BLKS, 256>>>(srcp, dstp);

    // layer 1 aggregation (writes relu to g_x)
    k_agg<<<agg_grid, 256>>>(b1, 0);
    // layer 2 GEMM (dis-scaled) -> g_xwh, then aggregation + stats
    k_gemm2<<<GEMM_BLKS, 256>>>(W2);
    k_agg<<<agg_grid, 256>>>(b2, 1);

    // graph layernorm
    k_ln<<<4096, 256>>>(lnw, lnb, out);
}

// round 17
// speedup vs baseline: 1.0086x; 1.0086x over previous
#include <cuda_runtime.h>
#include <cuda_fp16.h>

#define NN 100000
#define EE 1600000
#define C  64

#define SCAN_B 512
#define SCAN_NB ((NN + SCAN_B - 1) / SCAN_B)   // 196

// padded CSR (src-only): every node segment rounded up to multiple of 8
#define ECAP_E (EE + 8 * NN + 8)               // +8: prefetch overrun pad
#define ZR (NN * 32)                           // zero feature row base word

#define RPW 4
#define GEMM_BLKS ((NN / RPW) * 32 / 256)      // 3125
#define HIST_BLKS 2048
#define CLR_BLKS  512
#define FILL_BLKS 1536
#define SCALE_BLKS 512

// ---- scratch (device globals) ----
__device__ int       g_deg[NN];
__device__ int       g_off[NN];
__device__ int       g_cur[NN];
__device__ float     g_dis[NN];
__device__ int       g_bsum[SCAN_NB];
__device__ __align__(16) int g_srci[ECAP_E];        // src*32 per edge slot (pad -> ZR)
__device__ unsigned  g_xwh[(size_t)NN * 32 + 32];   // features half2-packed + zero row
__device__ float     g_x [(size_t)NN * C];          // activations (fp32)
__device__ double    g_stats[2];

// ---------------- init: deg=0, stats=0, zero feature row ----------------
__global__ void k_init0() {
    int i = blockIdx.x * blockDim.x + threadIdx.x;
    if (i < NN) g_deg[i] = 0;
    if (i < 2)  g_stats[i] = 0.0;
    if (i < 32) g_xwh[ZR + i] = 0u;
}

// ---------------- gemm device body (verified form) ----------------
__device__ __forceinline__ void gemm_body(const float* __restrict__ Xin,
                                          const float* __restrict__ W,
                                          int gblk, int scale_by_dis) {
    __shared__ float2 Wp[C][32];    // (W[k][2l], W[k][2l+1])
    __shared__ float4 Xs[8][C];     // Xs[warp][k] = 4 rows' col k
    for (int i = threadIdx.x; i < C * 32; i += blockDim.x) {
        int k = i >> 5, l = i & 31;
        Wp[k][l] = make_float2(W[k * C + 2 * l], W[k * C + 2 * l + 1]);
    }

    int warp = (gblk * 256 + threadIdx.x) >> 5;
    int w    = threadIdx.x >> 5;
    int lane = threadIdx.x & 31;
    int r0 = warp * RPW;

    {
        float2 xv[RPW];
#pragma unroll
        for (int i = 0; i < RPW; i++)
            xv[i] = *(const float2*)(Xin + (size_t)(r0 + i) * C + 2 * lane);
        Xs[w][2 * lane]     = make_float4(xv[0].x, xv[1].x, xv[2].x, xv[3].x);
        Xs[w][2 * lane + 1] = make_float4(xv[0].y, xv[1].y, xv[2].y, xv[3].y);
    }
    __syncthreads();

    float a0[RPW] = {0.f, 0.f, 0.f, 0.f};
    float a1[RPW] = {0.f, 0.f, 0.f, 0.f};
#pragma unroll
    for (int k = 0; k < C; k++) {
        float4 xk = Xs[w][k];          // LDS.128 broadcast
        float2 wv = Wp[k][lane];       // LDS.64 conflict-free
        a0[0] += xk.x * wv.x;  a1[0] += xk.x * wv.y;
        a0[1] += xk.y * wv.x;  a1[1] += xk.y * wv.y;
        a0[2] += xk.z * wv.x;  a1[2] += xk.z * wv.y;
        a0[3] += xk.w * wv.x;  a1[3] += xk.w * wv.y;
    }
#pragma unroll
    for (int i = 0; i < RPW; i++) {
        float d = scale_by_dis ? g_dis[r0 + i] : 1.0f;
        __half2 h = __float22half2_rn(make_float2(a0[i] * d, a1[i] * d));
        g_xwh[(size_t)(r0 + i) * 32 + lane] = *(unsigned*)&h;
    }
}

// ---------------- merged: gemm layer-1 + dst histogram + edge-array preset ----------------
__global__ void k_gemm_hist_clr(const float* __restrict__ X,
                                const float* __restrict__ W1,
                                const int* __restrict__ dst) {
    if (blockIdx.x < GEMM_BLKS) {
        gemm_body(X, W1, blockIdx.x, 0);
    } else if (blockIdx.x < GEMM_BLKS + HIST_BLKS) {
        int tid = (blockIdx.x - GEMM_BLKS) * blockDim.x + threadIdx.x;
        int stride = HIST_BLKS * blockDim.x;
        for (int e = tid; e < EE; e += stride)
            atomicAdd(&g_deg[dst[e]], 1);
    } else {
        int tid = (blockIdx.x - GEMM_BLKS - HIST_BLKS) * blockDim.x + threadIdx.x;
        int stride = CLR_BLKS * blockDim.x;
        int4 z = make_int4(ZR, ZR, ZR, ZR);
        int4* p = (int4*)g_srci;
        for (int i = tid; i < ECAP_E / 4; i += stride) p[i] = z;
    }
}

// ---------------- scan A: block-local exclusive scan of pad8(deg+1) ----------------
__global__ void k_scan_a() {
    __shared__ int sh[SCAN_B];
    int t = threadIdx.x;
    int i = blockIdx.x * SCAN_B + t;
    int v = (i < NN) ? ((g_deg[i] + 8) & ~7) : 0;
    sh[t] = v;
    __syncthreads();
    int acc = v;
#pragma unroll
    for (int d = 1; d < SCAN_B; d <<= 1) {
        int u = (t >= d) ? sh[t - d] : 0;
        __syncthreads();
        acc += u;
        sh[t] = acc;
        __syncthreads();
    }
    if (i < NN) g_off[i] = acc - v;
    if (t == SCAN_B - 1) g_bsum[blockIdx.x] = acc;
}

// ---------------- scan C (merged B): offsets, cur, dis; self-loop at slot off ----------------
__global__ void k_scan_c() {
    __shared__ int sh[256];
    int t = threadIdx.x;
    int v = (t < SCAN_NB) ? g_bsum[t] : 0;
    sh[t] = v;
    __syncthreads();
    int acc = v;
#pragma unroll
    for (int d = 1; d < 256; d <<= 1) {
        int u = (t >= d) ? sh[t - d] : 0;
        __syncthreads();
        acc += u;
        sh[t] = acc;
        __syncthreads();
    }
    sh[t] = acc - v;
    __syncthreads();

    int i = blockIdx.x * blockDim.x + t;
    if (i >= NN) return;
    int off = g_off[i] + sh[i / SCAN_B];
    g_off[i] = off;
    g_srci[off] = i * 32;            // self-loop (no atomic)
    g_cur[i] = off + 1;
    g_dis[i] = rsqrtf((float)(g_deg[i] + 1));
}

// ---------------- merged: CSR fill (vectorized, src only) + feature scale ----------------
__global__ void k_fill_scale(const int* __restrict__ src,
                             const int* __restrict__ dst) {
    if (blockIdx.x < FILL_BLKS) {
        int tid = blockIdx.x * blockDim.x + threadIdx.x;
        int stride = FILL_BLKS * blockDim.x;
        const int4* s4 = (const int4*)src;
        const int4* d4 = (const int4*)dst;
        for (int q = tid; q < EE / 4; q += stride) {    // EE divisible by 4
            int4 s = s4[q];
            int4 d = d4[q];
            g_srci[atomicAdd(&g_cur[d.x], 1)] = s.x * 32;
            g_srci[atomicAdd(&g_cur[d.y], 1)] = s.y * 32;
            g_srci[atomicAdd(&g_cur[d.z], 1)] = s.z * 32;
            g_srci[atomicAdd(&g_cur[d.w], 1)] = s.w * 32;
        }
    } else {
        // g_xwh[r] *= dis[r]
        int tid = (blockIdx.x - FILL_BLKS) * blockDim.x + threadIdx.x;
        int stride = SCALE_BLKS * blockDim.x;
        for (int i = tid; i < NN * 32; i += stride) {
            float d = g_dis[i >> 5];
            float2 v = __half22float2(*(__half2*)&g_xwh[i]);
            __half2 h = __float22half2_rn(make_float2(v.x * d, v.y * d));
            g_xwh[i] = *(unsigned*)&h;
        }
    }
}

// ---------------- gemm layer-2 (reads g_x, writes g_xwh pre-scaled by dis) ----------------
__global__ void k_gemm2(const float* __restrict__ W) {
    gemm_body(g_x, W, blockIdx.x, 1);
}

// ---------------- aggregate: warp/node, 8-edge batches, EDGE-PREFETCH pipeline ----------------
__global__ void k_agg(const float* __restrict__ bias, int phase) {
    int node = (blockIdx.x * blockDim.x + threadIdx.x) >> 5;
    int lane = threadIdx.x & 31;

    int   off = g_off[node];                  // multiple of 8
    int   nb  = (g_deg[node] + 8) >> 3;       // ceil((deg+1)/8)
    float di  = g_dis[node];
    float ax = 0.f, ay = 0.f;

    const int4* e4 = (const int4*)(g_srci + off);
    const unsigned* feat = g_xwh;

    // prime: edges of batch 0
    int4 p0 = e4[0], p1 = e4[1];

    for (int b = 0; b < nb; b++) {
        int rs[8] = {p0.x, p0.y, p0.z, p0.w, p1.x, p1.y, p1.z, p1.w};

        // 1) issue this batch's gathers
        unsigned hv[8];
#pragma unroll
        for (int j = 0; j < 8; j++) hv[j] = feat[rs[j] + lane];   // LDG.32

        // 2) issue next batch's edge loads while gathers are in flight
        e4 += 2;
        int4 n0 = e4[0], n1 = e4[1];          // pad guarantees in-bounds

        // 3) consume gathers
#pragma unroll
        for (int j = 0; j < 8; j++) {
            float2 v = __half22float2(*(__half2*)&hv[j]);
            ax += v.x;
            ay += v.y;
        }
        p0 = n0; p1 = n1;
    }

    float2 bb = *(const float2*)(bias + 2 * lane);
    float o0 = fmaxf(ax * di + bb.x, 0.f);
    float o1 = fmaxf(ay * di + bb.y, 0.f);
    *(float2*)(g_x + (size_t)node * C + 2 * lane) = make_float2(o0, o1);

    if (phase) {   // fused global sum/sumsq (exactly NN warps -> no early-out)
        float s  = o0 + o1;
        float s2 = o0 * o0 + o1 * o1;
#pragma unroll
        for (int o = 16; o; o >>= 1) {
            s  += __shfl_down_sync(0xffffffffu, s,  o);
            s2 += __shfl_down_sync(0xffffffffu, s2, o);
        }
        __shared__ float ss[8], ss2[8];
        int w = threadIdx.x >> 5;
        if (lane == 0) { ss[w] = s; ss2[w] = s2; }
        __syncthreads();
        if (w == 0 && lane < 8) {
            s  = ss[lane];
            s2 = ss2[lane];
#pragma unroll
            for (int o = 4; o; o >>= 1) {
                s  += __shfl_down_sync(0x000000ffu, s,  o);
                s2 += __shfl_down_sync(0x000000ffu, s2, o);
            }
            if (lane == 0) {
                atomicAdd(&g_stats[0], (double)s);
                atomicAdd(&g_stats[1], (double)s2);
            }
        }
    }
}

// ---------------- graph layernorm (float4) ----------------
__global__ void k_ln(const float* __restrict__ lnw,
                     const float* __restrict__ lnb,
                     float* __restrict__ out) {
    const int M4 = NN * C / 4;
    double mean = g_stats[0] / (double)(NN * C);
    double var  = g_stats[1] / (double)(NN * C) - mean * mean;
    float scale = (float)(1.0 / sqrt(var + 1e-5)) * lnw[0];
    float mu    = (float)mean;
    float shb   = lnb[0];
    const float4* xi = (const float4*)g_x;
    float4* xo = (float4*)out;
    int stride = gridDim.x * blockDim.x;
    for (int i = blockIdx.x * blockDim.x + threadIdx.x; i < M4; i += stride) {
        float4 v = xi[i];
        v.x = (v.x - mu) * scale + shb;
        v.y = (v.y - mu) * scale + shb;
        v.z = (v.z - mu) * scale + shb;
        v.w = (v.w - mu) * scale + shb;
        xo[i] = v;
    }
}

extern "C" void kernel_launch(void* const* d_in, const int* in_sizes, int n_in,
                              void* d_out, int out_size) {
    const float* X    = (const float*)d_in[0];
    const int*   edges= (const int*)d_in[1];   // int32 (JAX x64 disabled)
    const float* W1   = (const float*)d_in[2];
    const float* b1   = (const float*)d_in[3];
    const float* W2   = (const float*)d_in[4];
    const float* b2   = (const float*)d_in[5];
    const float* lnw  = (const float*)d_in[6];
    const float* lnb  = (const float*)d_in[7];
    float* out = (float*)d_out;

    const int* srcp = edges;        // edges[0]
    const int* dstp = edges + EE;   // edges[1]

    const int agg_grid = (NN * 32) / 256;      // exactly 12500

    k_init0<<<(NN + 255) / 256, 256>>>();
    k_gemm_hist_clr<<<GEMM_BLKS + HIST_BLKS + CLR_BLKS, 256>>>(X, W1, dstp);
    k_scan_a<<<SCAN_NB, SCAN_B>>>();
    k_scan_c<<<(NN + 255) / 256, 256>>>();
    k_fill_scale<<<FILL_BLKS + SCALE_BLKS, 256>>>(srcp, dstp);

    // layer 1 aggregation (writes relu to g_x)
    k_agg<<<agg_grid, 256>>>(b1, 0);
    // layer 2 GEMM (dis-scaled) -> g_xwh, then aggregation + stats
    k_gemm2<<<GEMM_BLKS, 256>>>(W2);
    k_agg<<<agg_grid, 256>>>(b2, 1);

    // graph layernorm
    k_ln<<<4096, 256>>>(lnw, lnb, out);
}